// round 12
// baseline (speedup 1.0000x reference)
#include <cuda_runtime.h>
#include <cstdint>
#include <math_constants.h>

#define BB 2
#define TQ 1024
#define TK 1024
#define DD 64
#define QW 4                 // queries per warp
#define WARPS 4              // 128 threads -> one warp per SMSP
#define THREADS (WARPS * 32)
#define QT (WARPS * QW)      // 16 query rows per block
#define KT 32                // key tile (lane = key)
#define KSPLIT 8
#define KB (TK / KSPLIT)     // 128 keys per block
#define NT (KB / KT)         // 4 tiles
#define NB 3                 // V smem buffers (depth-1 prefetch)
#define NROW (BB * TQ)       // 2048 output rows
#define QGRID (TQ / QT)      // 64
#define CHM 10               // chunks 0..CHM-1 via MUFU tanh; CHM..15 via FMA formula
#define CHF (16 - CHM)       // 6 formula chunks

// scratch: unnormalized partials per k-split + arrival counters
__device__ float g_po[KSPLIT][NROW * DD];   // 4 MB
__device__ float g_pl[KSPLIT][NROW];        // 64 KB
__device__ int   g_cnt[BB][QGRID];          // zero-init; self-resetting

__device__ __forceinline__ float tanh_fast(float x) {
    float y;
    asm("tanh.approx.f32 %0, %1;" : "=f"(y) : "f"(x));
    return y;
}
__device__ __forceinline__ float4 tanh4(float4 v) {
    return make_float4(tanh_fast(v.x), tanh_fast(v.y), tanh_fast(v.z), tanh_fast(v.w));
}

// FMA-pipe reciprocal: bit-trick seed (ALU) + 2 Newton steps. x in (0, 2].
__device__ __forceinline__ float rcp_fma(float x) {
    float y = __int_as_float(0x7EF311C3 - __float_as_int(x));
    float e = fmaf(-x, y, 1.0f); y = fmaf(y, e, y);
    e       = fmaf(-x, y, 1.0f); y = fmaf(y, e, y);
    return y;
}

// MUFU path: one query x one float4 chunk of scale-weighted tanh(q+v)
__device__ __forceinline__ void score4_mufu(const float4& qv, const float4& u,
                                            const float4& sc, float& a) {
    a = fmaf(sc.x, tanh_fast(qv.x + u.x), a);
    a = fmaf(sc.y, tanh_fast(qv.y + u.y), a);
    a = fmaf(sc.z, tanh_fast(qv.z + u.z), a);
    a = fmaf(sc.w, tanh_fast(qv.w + u.w), a);
}
// FMA path: tanh(q+v) = (Tq+Tv)/(1+Tq*Tv), all on FMA/ALU pipes
__device__ __forceinline__ void score4_form(const float4& tq, const float4& tv,
                                            const float4& sc, float& a) {
    a = fmaf(sc.x, (tq.x + tv.x) * rcp_fma(fmaf(tq.x, tv.x, 1.0f)), a);
    a = fmaf(sc.y, (tq.y + tv.y) * rcp_fma(fmaf(tq.y, tv.y, 1.0f)), a);
    a = fmaf(sc.z, (tq.z + tv.z) * rcp_fma(fmaf(tq.z, tv.z, 1.0f)), a);
    a = fmaf(sc.w, (tq.w + tv.w) * rcp_fma(fmaf(tq.w, tv.w, 1.0f)), a);
}

__device__ __forceinline__ void cp16(void* dst, const void* src) {
    unsigned d = (unsigned)__cvta_generic_to_shared(dst);
    asm volatile("cp.async.cg.shared.global [%0], [%1], 16;" :: "r"(d), "l"(src));
}
__device__ __forceinline__ void cp_commit() { asm volatile("cp.async.commit_group;"); }
template <int N>
__device__ __forceinline__ void cp_wait() { asm volatile("cp.async.wait_group %0;" :: "n"(N)); }

// V tile as float4 chunks, XOR-swizzled: chunk c of key k at k*16 + (c ^ (k&15)).
__device__ __forceinline__ void prefetch_tile(float4* dst, const float4* V4, int tt, int tid) {
    #pragma unroll
    for (int i = 0; i < 4; i++) {            // 512 chunks / 128 threads
        int id = tid + i * THREADS;
        int k = id >> 4, c = id & 15;
        cp16(&dst[k * 16 + (c ^ (k & 15))], &V4[(size_t)tt * KT * 16 + k * 16 + c]);
    }
    cp_commit();
}

__global__ __launch_bounds__(THREADS, 4)
void addattn_kernel(const float* __restrict__ Q,
                    const float* __restrict__ V,
                    const float* __restrict__ S,
                    float* __restrict__ O) {
    __shared__ __align__(16) float4 v_s[NB][KT * 16];   // 24 KB raw V
    __shared__ __align__(16) float4 tv_s[2][KT * 8];    // 8 KB tanh(V) formula chunks
    __shared__ __align__(16) float4 q_s[QT * 16];       // 4 KB (raw q for c<CHM, tanh(q) for c>=CHM)
    __shared__ __align__(16) float4 sc_s[16];           // 256 B
    __shared__ __align__(16) float  p_s[2][KT][QT];     // 4 KB  [buf][key][query]
    __shared__ int s_last;

    const int tid  = threadIdx.x;
    const int lane = tid & 31;
    const int warp = tid >> 5;
    const int b    = blockIdx.y;
    const int ks   = blockIdx.z;
    const int q0   = blockIdx.x * QT;

    const float4* Q4 = (const float4*)(Q + ((size_t)b * TQ + q0) * DD);
    q_s[tid]           = Q4[tid];             // QT*16 == 256 == 2*THREADS
    q_s[tid + THREADS] = Q4[tid + THREADS];
    if (tid < 16) sc_s[tid] = ((const float4*)S)[tid];

    const float4* V4 = (const float4*)(V + ((size_t)b * TK + (size_t)ks * KB) * DD);
    prefetch_tile(v_s[0], V4, 0, tid);       // group 0
    prefetch_tile(v_s[1], V4, 1, tid);       // group 1

    float l0 = 0.f, l1 = 0.f, l2 = 0.f, l3 = 0.f;
    float2 o0 = {0.f, 0.f}, o1 = {0.f, 0.f}, o2 = {0.f, 0.f}, o3 = {0.f, 0.f};
    const int sw   = lane & 15;
    const int c2   = lane >> 1, half = lane & 1;
    const int qa   = warp * QW;

    // Tv producer: tile tt raw -> tanh into tv_s[tt&1] (formula chunks only)
    auto make_tv = [&](int tt) {
        #pragma unroll
        for (int i = 0; i < 2; i++) {
            int id = tid + i * THREADS;
            if (id < KT * CHF) {
                int k = id / CHF, j = id % CHF;
                float4 u = v_s[tt % NB][k * 16 + ((CHM + j) ^ (k & 15))];
                tv_s[tt & 1][k * 8 + (j ^ (k & 7))] = tanh4(u);
            }
        }
    };

    // ---------- iter t = 0 : scores only ----------
    {
        cp_wait<1>();        // tile0 arrived (group1 may be pending)
        __syncthreads();     // q_s + tile0 visible to all threads
        // Tq transform: chunks CHM..15 of each query -> tanh(q)
        if (tid < QT * CHF) {
            int qi = tid / CHF, j = tid % CHF;
            int idx = qi * 16 + CHM + j;
            q_s[idx] = tanh4(q_s[idx]);
        }
        make_tv(0);
        __syncthreads();     // Tq + Tv(0) visible

        float a0 = 0.f, a1 = 0.f, a2 = 0.f, a3 = 0.f;
        #pragma unroll
        for (int c = 0; c < CHM; c++) {
            float4 sc = sc_s[c];
            float4 u  = v_s[0][lane * 16 + (c ^ sw)];
            score4_mufu(q_s[(qa + 0) * 16 + c], u, sc, a0);
            score4_mufu(q_s[(qa + 1) * 16 + c], u, sc, a1);
            score4_mufu(q_s[(qa + 2) * 16 + c], u, sc, a2);
            score4_mufu(q_s[(qa + 3) * 16 + c], u, sc, a3);
        }
        #pragma unroll
        for (int c = CHM; c < 16; c++) {
            float4 sc = sc_s[c];
            float4 tv = tv_s[0][lane * 8 + ((c - CHM) ^ (lane & 7))];
            score4_form(q_s[(qa + 0) * 16 + c], tv, sc, a0);
            score4_form(q_s[(qa + 1) * 16 + c], tv, sc, a1);
            score4_form(q_s[(qa + 2) * 16 + c], tv, sc, a2);
            score4_form(q_s[(qa + 3) * 16 + c], tv, sc, a3);
        }
        float p0 = __expf(a0), p1 = __expf(a1), p2 = __expf(a2), p3 = __expf(a3);
        l0 += p0; l1 += p1; l2 += p2; l3 += p3;
        *(float4*)&p_s[0][lane][qa] = make_float4(p0, p1, p2, p3);
        __syncwarp();
    }

    // ---------- iters t = 1..NT-1 : fused P1(t) + P3(t-1) ----------
    for (int t = 1; t < NT; ++t) {
        __syncthreads();     // iter t-1 fully retired -> buffer (t+1)%NB free
        if (t + 1 < NT) {
            prefetch_tile(v_s[(t + 1) % NB], V4, t + 1, tid);
            cp_wait<1>();    // tiles <= t arrived (t+1 in flight)
        } else {
            cp_wait<0>();    // everything arrived
        }
        __syncthreads();     // tile t visible to all threads
        make_tv(t);
        __syncthreads();     // Tv(t) visible

        const float4* vb = v_s[t % NB];
        const float4* vp = v_s[(t + NB - 1) % NB];     // tile t-1
        const int     pb = (t + 1) & 1;                // (t-1) & 1

        float a0 = 0.f, a1 = 0.f, a2 = 0.f, a3 = 0.f;
        #pragma unroll
        for (int c = 0; c < CHM; c++) {
            // --- phase 1 MUFU chunk (tile t) ---
            float4 sc = sc_s[c];
            float4 u  = vb[lane * 16 + (c ^ sw)];
            score4_mufu(q_s[(qa + 0) * 16 + c], u, sc, a0);
            score4_mufu(q_s[(qa + 1) * 16 + c], u, sc, a1);
            score4_mufu(q_s[(qa + 2) * 16 + c], u, sc, a2);
            score4_mufu(q_s[(qa + 3) * 16 + c], u, sc, a3);
            // --- phase 3 chunk (tile t-1), keys 2c, 2c+1 ---
            const int k0 = 2 * c, k1 = 2 * c + 1;
            float4 pa = *(const float4*)&p_s[pb][k0][qa];
            float4 pc = *(const float4*)&p_s[pb][k1][qa];
            float2 va = ((const float2*)&vp[k0 * 16 + (c2 ^ (k0 & 15))])[half];
            float2 vc = ((const float2*)&vp[k1 * 16 + (c2 ^ (k1 & 15))])[half];
            o0.x = fmaf(pa.x, va.x, o0.x); o0.y = fmaf(pa.x, va.y, o0.y);
            o1.x = fmaf(pa.y, va.x, o1.x); o1.y = fmaf(pa.y, va.y, o1.y);
            o2.x = fmaf(pa.z, va.x, o2.x); o2.y = fmaf(pa.z, va.y, o2.y);
            o3.x = fmaf(pa.w, va.x, o3.x); o3.y = fmaf(pa.w, va.y, o3.y);
            o0.x = fmaf(pc.x, vc.x, o0.x); o0.y = fmaf(pc.x, vc.y, o0.y);
            o1.x = fmaf(pc.y, vc.x, o1.x); o1.y = fmaf(pc.y, vc.y, o1.y);
            o2.x = fmaf(pc.z, vc.x, o2.x); o2.y = fmaf(pc.z, vc.y, o2.y);
            o3.x = fmaf(pc.w, vc.x, o3.x); o3.y = fmaf(pc.w, vc.y, o3.y);
        }
        #pragma unroll
        for (int c = CHM; c < 16; c++) {
            // --- phase 1 formula chunk (tile t) ---
            float4 sc = sc_s[c];
            float4 tv = tv_s[t & 1][lane * 8 + ((c - CHM) ^ (lane & 7))];
            score4_form(q_s[(qa + 0) * 16 + c], tv, sc, a0);
            score4_form(q_s[(qa + 1) * 16 + c], tv, sc, a1);
            score4_form(q_s[(qa + 2) * 16 + c], tv, sc, a2);
            score4_form(q_s[(qa + 3) * 16 + c], tv, sc, a3);
            // --- phase 3 chunk (tile t-1), keys 2c, 2c+1 ---
            const int k0 = 2 * c, k1 = 2 * c + 1;
            float4 pa = *(const float4*)&p_s[pb][k0][qa];
            float4 pc = *(const float4*)&p_s[pb][k1][qa];
            float2 va = ((const float2*)&vp[k0 * 16 + (c2 ^ (k0 & 15))])[half];
            float2 vc = ((const float2*)&vp[k1 * 16 + (c2 ^ (k1 & 15))])[half];
            o0.x = fmaf(pa.x, va.x, o0.x); o0.y = fmaf(pa.x, va.y, o0.y);
            o1.x = fmaf(pa.y, va.x, o1.x); o1.y = fmaf(pa.y, va.y, o1.y);
            o2.x = fmaf(pa.z, va.x, o2.x); o2.y = fmaf(pa.z, va.y, o2.y);
            o3.x = fmaf(pa.w, va.x, o3.x); o3.y = fmaf(pa.w, va.y, o3.y);
            o0.x = fmaf(pc.x, vc.x, o0.x); o0.y = fmaf(pc.x, vc.y, o0.y);
            o1.x = fmaf(pc.y, vc.x, o1.x); o1.y = fmaf(pc.y, vc.y, o1.y);
            o2.x = fmaf(pc.z, vc.x, o2.x); o2.y = fmaf(pc.z, vc.y, o2.y);
            o3.x = fmaf(pc.w, vc.x, o3.x); o3.y = fmaf(pc.w, vc.y, o3.y);
        }
        float p0 = __expf(a0), p1 = __expf(a1), p2 = __expf(a2), p3 = __expf(a3);
        l0 += p0; l1 += p1; l2 += p2; l3 += p3;
        *(float4*)&p_s[t & 1][lane][qa] = make_float4(p0, p1, p2, p3);
        __syncwarp();
    }

    // ---------- epilogue: P3 for tile NT-1 ----------
    {
        const float4* vp = v_s[(NT - 1) % NB];
        const int     pb = (NT - 1) & 1;
        #pragma unroll
        for (int c = 0; c < 16; c++) {
            const int k0 = 2 * c, k1 = 2 * c + 1;
            float4 pa = *(const float4*)&p_s[pb][k0][qa];
            float4 pc = *(const float4*)&p_s[pb][k1][qa];
            float2 va = ((const float2*)&vp[k0 * 16 + (c2 ^ (k0 & 15))])[half];
            float2 vc = ((const float2*)&vp[k1 * 16 + (c2 ^ (k1 & 15))])[half];
            o0.x = fmaf(pa.x, va.x, o0.x); o0.y = fmaf(pa.x, va.y, o0.y);
            o1.x = fmaf(pa.y, va.x, o1.x); o1.y = fmaf(pa.y, va.y, o1.y);
            o2.x = fmaf(pa.z, va.x, o2.x); o2.y = fmaf(pa.z, va.y, o2.y);
            o3.x = fmaf(pa.w, va.x, o3.x); o3.y = fmaf(pa.w, va.y, o3.y);
            o0.x = fmaf(pc.x, vc.x, o0.x); o0.y = fmaf(pc.x, vc.y, o0.y);
            o1.x = fmaf(pc.y, vc.x, o1.x); o1.y = fmaf(pc.y, vc.y, o1.y);
            o2.x = fmaf(pc.z, vc.x, o2.x); o2.y = fmaf(pc.z, vc.y, o2.y);
            o3.x = fmaf(pc.w, vc.x, o3.x); o3.y = fmaf(pc.w, vc.y, o3.y);
        }
    }

    // ---------- write unnormalized partials ----------
    #pragma unroll
    for (int off = 16; off > 0; off >>= 1) {
        l0 += __shfl_xor_sync(0xffffffffu, l0, off);
        l1 += __shfl_xor_sync(0xffffffffu, l1, off);
        l2 += __shfl_xor_sync(0xffffffffu, l2, off);
        l3 += __shfl_xor_sync(0xffffffffu, l3, off);
    }
    const int row0 = b * TQ + q0 + qa;
    ((float2*)&g_po[ks][(size_t)(row0 + 0) * DD])[lane] = o0;
    ((float2*)&g_po[ks][(size_t)(row0 + 1) * DD])[lane] = o1;
    ((float2*)&g_po[ks][(size_t)(row0 + 2) * DD])[lane] = o2;
    ((float2*)&g_po[ks][(size_t)(row0 + 3) * DD])[lane] = o3;
    if (lane == 0) {
        g_pl[ks][row0 + 0] = l0;
        g_pl[ks][row0 + 1] = l1;
        g_pl[ks][row0 + 2] = l2;
        g_pl[ks][row0 + 3] = l3;
    }

    // ---------- fused combine: last-arriving split block reduces ----------
    __threadfence();                               // release partials
    if (tid == 0) {
        int old = atomicAdd(&g_cnt[b][blockIdx.x], 1);
        s_last = (old == KSPLIT - 1) ? 1 : 0;
    }
    __syncthreads();
    if (s_last) {
        __threadfence();                           // acquire other blocks' partials
        #pragma unroll
        for (int i = 0; i < 2; i++) {
            const int id  = tid + i * THREADS;
            const int r   = id >> 4;               // 0..15
            const int d4  = id & 15;               // float4 index 0..15
            const int row = b * TQ + q0 + r;
            float l = 0.f;
            #pragma unroll
            for (int s = 0; s < KSPLIT; s++) l += g_pl[s][row];
            float4 acc = make_float4(0.f, 0.f, 0.f, 0.f);
            #pragma unroll
            for (int s = 0; s < KSPLIT; s++) {
                float4 v = ((const float4*)&g_po[s][(size_t)row * DD])[d4];
                acc.x += v.x; acc.y += v.y; acc.z += v.z; acc.w += v.w;
            }
            const float inv = 1.f / l;
            float4 rr; rr.x = acc.x * inv; rr.y = acc.y * inv;
            rr.z = acc.z * inv; rr.w = acc.w * inv;
            ((float4*)(O + (size_t)row * DD))[d4] = rr;
        }
        __threadfence();                           // order reads before reset
        if (tid == 0) g_cnt[b][blockIdx.x] = 0;    // reset for next graph replay
    }
}

extern "C" void kernel_launch(void* const* d_in, const int* in_sizes, int n_in,
                              void* d_out, int out_size) {
    const float* Q = (const float*)d_in[0];   // query [B, Tq, D] f32
    const float* V = (const float*)d_in[1];   // value [B, Tk, D] f32
    const float* S = (const float*)d_in[2];   // scale [D] f32
    float* O = (float*)d_out;                 // out   [B, Tq, D] f32
    dim3 grid(QGRID, BB, KSPLIT);             // 64 x 2 x 8 = 1024 blocks
    addattn_kernel<<<grid, THREADS>>>(Q, V, S, O);
}

// round 13
// speedup vs baseline: 1.1994x; 1.1994x over previous
#include <cuda_runtime.h>
#include <cstdint>
#include <math_constants.h>

#define BB 2
#define TQ 1024
#define TK 1024
#define DD 64
#define QW 2                 // queries per warp
#define WARPS 4              // 128 threads -> one warp per SMSP
#define THREADS (WARPS * 32)
#define QT (WARPS * QW)      // 8 query rows per block
#define KT 32                // key tile (lane = key)
#define KSPLIT 4
#define KB (TK / KSPLIT)     // 256 keys per block
#define NT (KB / KT)         // 8 tiles
#define NB 4                 // V smem buffers
#define NROW (BB * TQ)       // 2048 output rows
#define QGRID (TQ / QT)      // 128

// scratch: unnormalized partials per k-split + arrival counters
__device__ float g_po[KSPLIT][NROW * DD];   // 2 MB
__device__ float g_pl[KSPLIT][NROW];        // 32 KB
__device__ int   g_cnt[BB][QGRID];          // zero-init; self-resetting

__device__ __forceinline__ float tanh_fast(float x) {
    float y;
    asm("tanh.approx.f32 %0, %1;" : "=f"(y) : "f"(x));
    return y;
}

__device__ __forceinline__ void cp16(void* dst, const void* src) {
    unsigned d = (unsigned)__cvta_generic_to_shared(dst);
    asm volatile("cp.async.cg.shared.global [%0], [%1], 16;" :: "r"(d), "l"(src));
}
__device__ __forceinline__ void cp_commit() { asm volatile("cp.async.commit_group;"); }
template <int N>
__device__ __forceinline__ void cp_wait() { asm volatile("cp.async.wait_group %0;" :: "n"(N)); }

// V tile as float4 chunks, XOR-swizzled: chunk c of key k at k*16 + (c ^ (k&15)).
__device__ __forceinline__ void prefetch_tile(float4* dst, const float4* V4, int tt, int tid) {
    #pragma unroll
    for (int i = 0; i < 4; i++) {            // 512 chunks / 128 threads
        int id = tid + i * THREADS;
        int k = id >> 4, c = id & 15;
        cp16(&dst[k * 16 + (c ^ (k & 15))], &V4[(size_t)tt * KT * 16 + k * 16 + c]);
    }
    cp_commit();
}

__global__ __launch_bounds__(THREADS, 5)
void addattn_kernel(const float* __restrict__ Q,
                    const float* __restrict__ V,
                    const float* __restrict__ S,
                    float* __restrict__ O) {
    __shared__ __align__(16) float4 v_s[NB][KT * 16];   // 32 KB
    __shared__ __align__(16) float4 q_s[QT * 16];       // 2 KB
    __shared__ __align__(16) float4 sc_s[16];           // 256 B
    __shared__ __align__(16) float  p_s[2][QT][KT];     // 2 KB
    __shared__ int s_last;

    const int tid  = threadIdx.x;
    const int lane = tid & 31;
    const int warp = tid >> 5;
    const int b    = blockIdx.y;
    const int ks   = blockIdx.z;
    const int q0   = blockIdx.x * QT;

    const float4* Q4 = (const float4*)(Q + ((size_t)b * TQ + q0) * DD);
    q_s[tid] = Q4[tid];                       // QT*16 == 128 == THREADS
    if (tid < 16) sc_s[tid] = ((const float4*)S)[tid];

    const float4* V4 = (const float4*)(V + ((size_t)b * TK + (size_t)ks * KB) * DD);
    prefetch_tile(v_s[0], V4, 0, tid);
    prefetch_tile(v_s[1], V4, 1, tid);

    float l0 = 0.f, l1 = 0.f;
    float ox0 = 0.f, oy0 = 0.f, ox1 = 0.f, oy1 = 0.f;
    const int sw   = lane & 15;
    const int c2   = lane >> 1, half = lane & 1;
    const int qa   = warp * QW;

    // ---------- iter t = 0 : scores only ----------
    {
        cp_wait<1>();
        __syncthreads();
        prefetch_tile(v_s[2], V4, 2, tid);
        const float4* vb = v_s[0];
        float a00 = 0.f, a10 = 0.f;
        #pragma unroll
        for (int c = 0; c < 16; c++) {
            float4 qv0 = q_s[(qa + 0) * 16 + c];
            float4 qv1 = q_s[(qa + 1) * 16 + c];
            float4 sc  = sc_s[c];
            float4 u   = vb[lane * 16 + (c ^ sw)];
            a00 = fmaf(sc.x, tanh_fast(qv0.x + u.x), a00);
            a00 = fmaf(sc.y, tanh_fast(qv0.y + u.y), a00);
            a00 = fmaf(sc.z, tanh_fast(qv0.z + u.z), a00);
            a00 = fmaf(sc.w, tanh_fast(qv0.w + u.w), a00);
            a10 = fmaf(sc.x, tanh_fast(qv1.x + u.x), a10);
            a10 = fmaf(sc.y, tanh_fast(qv1.y + u.y), a10);
            a10 = fmaf(sc.z, tanh_fast(qv1.z + u.z), a10);
            a10 = fmaf(sc.w, tanh_fast(qv1.w + u.w), a10);
        }
        float p00 = __expf(a00), p10 = __expf(a10);
        l0 += p00; l1 += p10;
        p_s[0][qa + 0][lane] = p00;
        p_s[0][qa + 1][lane] = p10;
        __syncwarp();
    }

    // ---------- iters t = 1..NT-1 : fused P1(t) + P3(t-1) ----------
    for (int t = 1; t < NT; ++t) {
        if (t + 1 < NT) cp_wait<1>(); else cp_wait<0>();
        __syncthreads();
        if (t + 2 < NT) prefetch_tile(v_s[(t + 2) & 3], V4, t + 2, tid);

        const float4* vb  = v_s[t & 3];
        const float4* vp  = v_s[(t + 3) & 3];          // (t-1) & 3
        const float*  pr0 = p_s[(t + 1) & 1][qa + 0];  // (t-1) & 1
        const float*  pr1 = p_s[(t + 1) & 1][qa + 1];

        float a00 = 0.f, a10 = 0.f;
        #pragma unroll
        for (int c = 0; c < 16; c++) {
            // --- phase 1 chunk (tile t), 8 tanh ---
            float4 qv0 = q_s[(qa + 0) * 16 + c];
            float4 qv1 = q_s[(qa + 1) * 16 + c];
            float4 sc  = sc_s[c];
            float4 u   = vb[lane * 16 + (c ^ sw)];
            a00 = fmaf(sc.x, tanh_fast(qv0.x + u.x), a00);
            a00 = fmaf(sc.y, tanh_fast(qv0.y + u.y), a00);
            a00 = fmaf(sc.z, tanh_fast(qv0.z + u.z), a00);
            a00 = fmaf(sc.w, tanh_fast(qv0.w + u.w), a00);
            a10 = fmaf(sc.x, tanh_fast(qv1.x + u.x), a10);
            a10 = fmaf(sc.y, tanh_fast(qv1.y + u.y), a10);
            a10 = fmaf(sc.z, tanh_fast(qv1.z + u.z), a10);
            a10 = fmaf(sc.w, tanh_fast(qv1.w + u.w), a10);

            // --- phase 3 chunk (tile t-1), keys 2c, 2c+1 ---
            {
                const int k0 = 2 * c, k1 = 2 * c + 1;
                float2 pq0 = *(const float2*)&pr0[k0];
                float2 pq1 = *(const float2*)&pr1[k0];
                float2 va = ((const float2*)&vp[k0 * 16 + (c2 ^ (k0 & 15))])[half];
                float2 vc = ((const float2*)&vp[k1 * 16 + (c2 ^ (k1 & 15))])[half];
                ox0 = fmaf(pq0.x, va.x, ox0); oy0 = fmaf(pq0.x, va.y, oy0);
                ox1 = fmaf(pq1.x, va.x, ox1); oy1 = fmaf(pq1.x, va.y, oy1);
                ox0 = fmaf(pq0.y, vc.x, ox0); oy0 = fmaf(pq0.y, vc.y, oy0);
                ox1 = fmaf(pq1.y, vc.x, ox1); oy1 = fmaf(pq1.y, vc.y, oy1);
            }
        }
        float p00 = __expf(a00), p10 = __expf(a10);
        l0 += p00; l1 += p10;
        p_s[t & 1][qa + 0][lane] = p00;
        p_s[t & 1][qa + 1][lane] = p10;
        __syncwarp();
    }

    // ---------- epilogue: P3 for tile NT-1 ----------
    {
        const float4* vp  = v_s[(NT - 1) & 3];
        const float*  pr0 = p_s[(NT - 1) & 1][qa + 0];
        const float*  pr1 = p_s[(NT - 1) & 1][qa + 1];
        #pragma unroll
        for (int c = 0; c < 16; c++) {
            const int k0 = 2 * c, k1 = 2 * c + 1;
            float2 pq0 = *(const float2*)&pr0[k0];
            float2 pq1 = *(const float2*)&pr1[k0];
            float2 va = ((const float2*)&vp[k0 * 16 + (c2 ^ (k0 & 15))])[half];
            float2 vc = ((const float2*)&vp[k1 * 16 + (c2 ^ (k1 & 15))])[half];
            ox0 = fmaf(pq0.x, va.x, ox0); oy0 = fmaf(pq0.x, va.y, oy0);
            ox1 = fmaf(pq1.x, va.x, ox1); oy1 = fmaf(pq1.x, va.y, oy1);
            ox0 = fmaf(pq0.y, vc.x, ox0); oy0 = fmaf(pq0.y, vc.y, oy0);
            ox1 = fmaf(pq1.y, vc.x, ox1); oy1 = fmaf(pq1.y, vc.y, oy1);
        }
    }

    // ---------- write unnormalized partials ----------
    #pragma unroll
    for (int off = 16; off > 0; off >>= 1) {
        l0 += __shfl_xor_sync(0xffffffffu, l0, off);
        l1 += __shfl_xor_sync(0xffffffffu, l1, off);
    }
    const int row0 = b * TQ + q0 + qa;
    {
        float2 r; r.x = ox0; r.y = oy0;
        ((float2*)&g_po[ks][(size_t)(row0 + 0) * DD])[lane] = r;
        if (lane == 0) g_pl[ks][row0 + 0] = l0;
    }
    {
        float2 r; r.x = ox1; r.y = oy1;
        ((float2*)&g_po[ks][(size_t)(row0 + 1) * DD])[lane] = r;
        if (lane == 0) g_pl[ks][row0 + 1] = l1;
    }

    // ---------- fused combine: last-arriving split block reduces ----------
    __threadfence();                               // release partials
    if (tid == 0) {
        int old = atomicAdd(&g_cnt[b][blockIdx.x], 1);
        s_last = (old == KSPLIT - 1) ? 1 : 0;
    }
    __syncthreads();
    if (s_last) {
        __threadfence();                           // acquire other blocks' partials
        // 8 rows x 64 dims = 512 floats; 128 threads x one float4 each
        const int r   = tid >> 4;                  // 0..7
        const int d4  = tid & 15;                  // float4 index 0..15
        const int row = b * TQ + q0 + r;
        float l = g_pl[0][row] + g_pl[1][row] + g_pl[2][row] + g_pl[3][row];
        float4 acc = make_float4(0.f, 0.f, 0.f, 0.f);
        #pragma unroll
        for (int s = 0; s < KSPLIT; s++) {
            float4 v = ((const float4*)&g_po[s][(size_t)row * DD])[d4];
            acc.x += v.x; acc.y += v.y; acc.z += v.z; acc.w += v.w;
        }
        const float inv = 1.f / l;
        float4 rr; rr.x = acc.x * inv; rr.y = acc.y * inv;
        rr.z = acc.z * inv; rr.w = acc.w * inv;
        ((float4*)(O + (size_t)row * DD))[d4] = rr;
        __threadfence();                           // order reads before reset
        if (tid == 0) g_cnt[b][blockIdx.x] = 0;    // reset for next graph replay
    }
}

extern "C" void kernel_launch(void* const* d_in, const int* in_sizes, int n_in,
                              void* d_out, int out_size) {
    const float* Q = (const float*)d_in[0];   // query [B, Tq, D] f32
    const float* V = (const float*)d_in[1];   // value [B, Tk, D] f32
    const float* S = (const float*)d_in[2];   // scale [D] f32
    float* O = (float*)d_out;                 // out   [B, Tq, D] f32
    dim3 grid(QGRID, BB, KSPLIT);             // 128 x 2 x 4 = 1024 blocks
    addattn_kernel<<<grid, THREADS>>>(Q, V, S, O);
}

// round 14
// speedup vs baseline: 1.2610x; 1.0513x over previous
#include <cuda_runtime.h>
#include <cstdint>
#include <math_constants.h>

#define BB 2
#define TQ 1024
#define TK 1024
#define DD 64
#define QW 4                 // queries per warp
#define WARPS 4              // 128 threads -> one warp per SMSP
#define THREADS (WARPS * 32)
#define QT (WARPS * QW)      // 16 query rows per block
#define KT 32                // key tile (lane = key)
#define KSPLIT 8
#define KB (TK / KSPLIT)     // 128 keys per block
#define NT (KB / KT)         // 4 tiles
#define NB 4                 // V smem buffers
#define NROW (BB * TQ)       // 2048 output rows
#define QGRID (TQ / QT)      // 64

// scratch: unnormalized partials per k-split + arrival counters
__device__ float g_po[KSPLIT][NROW * DD];   // 4 MB
__device__ float g_pl[KSPLIT][NROW];        // 64 KB
__device__ int   g_cnt[BB][QGRID];          // zero-init; self-resetting

__device__ __forceinline__ float tanh_fast(float x) {
    float y;
    asm("tanh.approx.f32 %0, %1;" : "=f"(y) : "f"(x));
    return y;
}

// one query x one float4 dim-chunk of scale-weighted tanh
__device__ __forceinline__ void score4(const float4& qv, const float4& u,
                                       const float4& sc, float& a) {
    a = fmaf(sc.x, tanh_fast(qv.x + u.x), a);
    a = fmaf(sc.y, tanh_fast(qv.y + u.y), a);
    a = fmaf(sc.z, tanh_fast(qv.z + u.z), a);
    a = fmaf(sc.w, tanh_fast(qv.w + u.w), a);
}

__device__ __forceinline__ void cp16(void* dst, const void* src) {
    unsigned d = (unsigned)__cvta_generic_to_shared(dst);
    asm volatile("cp.async.cg.shared.global [%0], [%1], 16;" :: "r"(d), "l"(src));
}
__device__ __forceinline__ void cp_commit() { asm volatile("cp.async.commit_group;"); }
template <int N>
__device__ __forceinline__ void cp_wait() { asm volatile("cp.async.wait_group %0;" :: "n"(N)); }

// V tile as float4 chunks, XOR-swizzled: chunk c of key k at k*16 + (c ^ (k&15)).
__device__ __forceinline__ void prefetch_tile(float4* dst, const float4* V4, int tt, int tid) {
    #pragma unroll
    for (int i = 0; i < 4; i++) {            // 512 chunks / 128 threads
        int id = tid + i * THREADS;
        int k = id >> 4, c = id & 15;
        cp16(&dst[k * 16 + (c ^ (k & 15))], &V4[(size_t)tt * KT * 16 + k * 16 + c]);
    }
    cp_commit();
}

__global__ __launch_bounds__(THREADS, 4)
void addattn_kernel(const float* __restrict__ Q,
                    const float* __restrict__ V,
                    const float* __restrict__ S,
                    float* __restrict__ O) {
    __shared__ __align__(16) float4 v_s[NB][KT * 16];   // 32 KB
    __shared__ __align__(16) float4 q_s[QT * 16];       // 4 KB
    __shared__ __align__(16) float4 sc_s[16];           // 256 B
    __shared__ __align__(16) float  p_s[2][KT][QT];     // 4 KB  [buf][key][query]
    __shared__ int s_last;

    const int tid  = threadIdx.x;
    const int lane = tid & 31;
    const int warp = tid >> 5;
    const int b    = blockIdx.y;
    const int ks   = blockIdx.z;
    const int q0   = blockIdx.x * QT;

    const float4* Q4 = (const float4*)(Q + ((size_t)b * TQ + q0) * DD);
    q_s[tid]           = Q4[tid];             // QT*16 == 256 == 2*THREADS
    q_s[tid + THREADS] = Q4[tid + THREADS];
    if (tid < 16) sc_s[tid] = ((const float4*)S)[tid];

    const float4* V4 = (const float4*)(V + ((size_t)b * TK + (size_t)ks * KB) * DD);
    prefetch_tile(v_s[0], V4, 0, tid);
    prefetch_tile(v_s[1], V4, 1, tid);

    float l0 = 0.f, l1 = 0.f, l2 = 0.f, l3 = 0.f;
    float2 o0 = {0.f, 0.f}, o1 = {0.f, 0.f}, o2 = {0.f, 0.f}, o3 = {0.f, 0.f};
    const int sw   = lane & 15;
    const int c2   = lane >> 1, half = lane & 1;
    const int qa   = warp * QW;

    // ---------- iter t = 0 : scores only ----------
    {
        cp_wait<1>();
        __syncthreads();
        prefetch_tile(v_s[2], V4, 2, tid);
        const float4* vb = v_s[0];
        float a0 = 0.f, a1 = 0.f, a2 = 0.f, a3 = 0.f;
        #pragma unroll
        for (int c = 0; c < 16; c++) {
            float4 sc = sc_s[c];
            float4 u  = vb[lane * 16 + (c ^ sw)];
            score4(q_s[(qa + 0) * 16 + c], u, sc, a0);
            score4(q_s[(qa + 1) * 16 + c], u, sc, a1);
            score4(q_s[(qa + 2) * 16 + c], u, sc, a2);
            score4(q_s[(qa + 3) * 16 + c], u, sc, a3);
        }
        float p0 = __expf(a0), p1 = __expf(a1), p2 = __expf(a2), p3 = __expf(a3);
        l0 += p0; l1 += p1; l2 += p2; l3 += p3;
        *(float4*)&p_s[0][lane][qa] = make_float4(p0, p1, p2, p3);
        __syncwarp();
    }

    // ---------- iters t = 1..NT-1 : fused P1(t) + P3(t-1) ----------
    for (int t = 1; t < NT; ++t) {
        if (t + 1 < NT) cp_wait<1>(); else cp_wait<0>();
        __syncthreads();
        if (t + 2 < NT) prefetch_tile(v_s[(t + 2) & 3], V4, t + 2, tid);

        const float4* vb = v_s[t & 3];
        const float4* vp = v_s[(t + 3) & 3];           // (t-1) & 3
        const int     pb = (t + 1) & 1;                // (t-1) & 1

        float a0 = 0.f, a1 = 0.f, a2 = 0.f, a3 = 0.f;
        #pragma unroll
        for (int c = 0; c < 16; c++) {
            // --- phase 1 chunk (tile t): 16 tanh ---
            float4 sc = sc_s[c];
            float4 u  = vb[lane * 16 + (c ^ sw)];
            score4(q_s[(qa + 0) * 16 + c], u, sc, a0);
            score4(q_s[(qa + 1) * 16 + c], u, sc, a1);
            score4(q_s[(qa + 2) * 16 + c], u, sc, a2);
            score4(q_s[(qa + 3) * 16 + c], u, sc, a3);

            // --- phase 3 chunk (tile t-1), keys 2c, 2c+1, 4 queries ---
            {
                const int k0 = 2 * c, k1 = 2 * c + 1;
                float4 pa = *(const float4*)&p_s[pb][k0][qa];
                float4 pc = *(const float4*)&p_s[pb][k1][qa];
                float2 va = ((const float2*)&vp[k0 * 16 + (c2 ^ (k0 & 15))])[half];
                float2 vc = ((const float2*)&vp[k1 * 16 + (c2 ^ (k1 & 15))])[half];
                o0.x = fmaf(pa.x, va.x, o0.x); o0.y = fmaf(pa.x, va.y, o0.y);
                o1.x = fmaf(pa.y, va.x, o1.x); o1.y = fmaf(pa.y, va.y, o1.y);
                o2.x = fmaf(pa.z, va.x, o2.x); o2.y = fmaf(pa.z, va.y, o2.y);
                o3.x = fmaf(pa.w, va.x, o3.x); o3.y = fmaf(pa.w, va.y, o3.y);
                o0.x = fmaf(pc.x, vc.x, o0.x); o0.y = fmaf(pc.x, vc.y, o0.y);
                o1.x = fmaf(pc.y, vc.x, o1.x); o1.y = fmaf(pc.y, vc.y, o1.y);
                o2.x = fmaf(pc.z, vc.x, o2.x); o2.y = fmaf(pc.z, vc.y, o2.y);
                o3.x = fmaf(pc.w, vc.x, o3.x); o3.y = fmaf(pc.w, vc.y, o3.y);
            }
        }
        float p0 = __expf(a0), p1 = __expf(a1), p2 = __expf(a2), p3 = __expf(a3);
        l0 += p0; l1 += p1; l2 += p2; l3 += p3;
        *(float4*)&p_s[t & 1][lane][qa] = make_float4(p0, p1, p2, p3);
        __syncwarp();
    }

    // ---------- epilogue: P3 for tile NT-1 ----------
    {
        const float4* vp = v_s[(NT - 1) & 3];
        const int     pb = (NT - 1) & 1;
        #pragma unroll
        for (int c = 0; c < 16; c++) {
            const int k0 = 2 * c, k1 = 2 * c + 1;
            float4 pa = *(const float4*)&p_s[pb][k0][qa];
            float4 pc = *(const float4*)&p_s[pb][k1][qa];
            float2 va = ((const float2*)&vp[k0 * 16 + (c2 ^ (k0 & 15))])[half];
            float2 vc = ((const float2*)&vp[k1 * 16 + (c2 ^ (k1 & 15))])[half];
            o0.x = fmaf(pa.x, va.x, o0.x); o0.y = fmaf(pa.x, va.y, o0.y);
            o1.x = fmaf(pa.y, va.x, o1.x); o1.y = fmaf(pa.y, va.y, o1.y);
            o2.x = fmaf(pa.z, va.x, o2.x); o2.y = fmaf(pa.z, va.y, o2.y);
            o3.x = fmaf(pa.w, va.x, o3.x); o3.y = fmaf(pa.w, va.y, o3.y);
            o0.x = fmaf(pc.x, vc.x, o0.x); o0.y = fmaf(pc.x, vc.y, o0.y);
            o1.x = fmaf(pc.y, vc.x, o1.x); o1.y = fmaf(pc.y, vc.y, o1.y);
            o2.x = fmaf(pc.z, vc.x, o2.x); o2.y = fmaf(pc.z, vc.y, o2.y);
            o3.x = fmaf(pc.w, vc.x, o3.x); o3.y = fmaf(pc.w, vc.y, o3.y);
        }
    }

    // ---------- write unnormalized partials ----------
    #pragma unroll
    for (int off = 16; off > 0; off >>= 1) {
        l0 += __shfl_xor_sync(0xffffffffu, l0, off);
        l1 += __shfl_xor_sync(0xffffffffu, l1, off);
        l2 += __shfl_xor_sync(0xffffffffu, l2, off);
        l3 += __shfl_xor_sync(0xffffffffu, l3, off);
    }
    const int row0 = b * TQ + q0 + qa;
    ((float2*)&g_po[ks][(size_t)(row0 + 0) * DD])[lane] = o0;
    ((float2*)&g_po[ks][(size_t)(row0 + 1) * DD])[lane] = o1;
    ((float2*)&g_po[ks][(size_t)(row0 + 2) * DD])[lane] = o2;
    ((float2*)&g_po[ks][(size_t)(row0 + 3) * DD])[lane] = o3;
    if (lane == 0) {
        g_pl[ks][row0 + 0] = l0;
        g_pl[ks][row0 + 1] = l1;
        g_pl[ks][row0 + 2] = l2;
        g_pl[ks][row0 + 3] = l3;
    }

    // ---------- fused combine: single-thread release/acquire handshake ----------
    __syncthreads();                               // block's partial writes hb-before here
    if (tid == 0) {
        __threadfence();                           // release: publish whole block's writes
        int old = atomicAdd(&g_cnt[b][blockIdx.x], 1);
        int last = (old == KSPLIT - 1) ? 1 : 0;
        if (last) __threadfence();                 // acquire: see all other blocks' partials
        s_last = last;
    }
    __syncthreads();                               // propagate visibility block-wide
    if (s_last) {
        // 16 rows x 64 dims = 1024 floats; 128 threads x two float4 each
        #pragma unroll
        for (int i = 0; i < 2; i++) {
            const int id  = tid + i * THREADS;
            const int r   = id >> 4;               // 0..15
            const int d4  = id & 15;               // float4 index 0..15
            const int row = b * TQ + q0 + r;
            float l = 0.f;
            #pragma unroll
            for (int s = 0; s < KSPLIT; s++) l += g_pl[s][row];
            float4 acc = make_float4(0.f, 0.f, 0.f, 0.f);
            #pragma unroll
            for (int s = 0; s < KSPLIT; s++) {
                float4 v = ((const float4*)&g_po[s][(size_t)row * DD])[d4];
                acc.x += v.x; acc.y += v.y; acc.z += v.z; acc.w += v.w;
            }
            const float inv = 1.f / l;
            float4 rr; rr.x = acc.x * inv; rr.y = acc.y * inv;
            rr.z = acc.z * inv; rr.w = acc.w * inv;
            ((float4*)(O + (size_t)row * DD))[d4] = rr;
        }
        if (tid == 0) g_cnt[b][blockIdx.x] = 0;    // reset for next graph replay
    }
}

extern "C" void kernel_launch(void* const* d_in, const int* in_sizes, int n_in,
                              void* d_out, int out_size) {
    const float* Q = (const float*)d_in[0];   // query [B, Tq, D] f32
    const float* V = (const float*)d_in[1];   // value [B, Tk, D] f32
    const float* S = (const float*)d_in[2];   // scale [D] f32
    float* O = (float*)d_out;                 // out   [B, Tq, D] f32
    dim3 grid(QGRID, BB, KSPLIT);             // 64 x 2 x 8 = 1024 blocks
    addattn_kernel<<<grid, THREADS>>>(Q, V, S, O);
}